// round 8
// baseline (speedup 1.0000x reference)
#include <cuda_runtime.h>
#include <cuda_fp16.h>

#define NMAX 50000
#define EMAX 800000
#define GMAX 2500
#define ETOT (EMAX + NMAX)
#define SCAN_B 512
#define SCAN_NB ((NMAX + SCAN_B - 1) / SCAN_B)   // 98

// packed dual-fp32 helpers (sm_100+ PTX)
#define PACK2(out, f) asm("mov.b64 %0, {%1, %1};" : "=l"(out) : "r"(__float_as_uint(f)))
#define FMA2(d, a, b) asm("fma.rn.f32x2 %0, %1, %2, %0;" : "+l"(d) : "l"(a), "l"(b))
#define UNPACK2(lo, hi, v) asm("mov.b64 {%0, %1}, %2;" : "=r"(lo), "=r"(hi) : "l"(v))

// ---------------- scratch (device globals; zero-initialized at load) --------------
// INVARIANT: g_deg, g_fill, g_gsum, g_gcnt, g_ctr1, g_ctr2 are ZERO on entry to
// every kernel_launch call; each call re-zeros them after last use (zero-at-exit).
__device__ uint2 g_h16[NMAX * 32];     // per-layer hidden, fp16
__device__ float g_f0[NMAX * 64];      // layer output ping (fp32)
__device__ float g_f1[NMAX * 64];      // layer output pong
__device__ float g_att[NMAX * 4];      // per node: a_src0, a_src1, a_dst0, a_dst1
__device__ int   g_rp[NMAX + 1];       // CSR row_ptr (pre block-offset)
__device__ int   g_deg[NMAX];          // edge-only degree (self loop added as +1)
__device__ int   g_fill[NMAX];
__device__ int   g_csrc[ETOT];         // CSR src indices
__device__ float g_gsum[GMAX];
__device__ float g_gcnt[GMAX];
__device__ int   g_bsum[SCAN_NB + 1];
__device__ int   g_boff[SCAN_NB + 1];
__device__ int   g_ctr1;               // scan last-block ticket
__device__ int   g_ctr2;               // agg3 last-block ticket

// --------- deg count (4 edges/thread) + graph-size count for mean pooling --------
__global__ void k_count(const int* __restrict__ ei, const int* __restrict__ batch,
                        int E, int n) {
  int i = blockIdx.x * blockDim.x + threadIdx.x;
  int E4 = E >> 2;
  if (i < E4) {
    int4 d = ((const int4*)(ei + E))[i];
    atomicAdd(&g_deg[d.x], 1);
    atomicAdd(&g_deg[d.y], 1);
    atomicAdd(&g_deg[d.z], 1);
    atomicAdd(&g_deg[d.w], 1);
  } else {
    int j = (E4 << 2) + (i - E4);
    if (j < E) atomicAdd(&g_deg[ei[E + j]], 1);
  }
  if (i < n) atomicAdd(&g_gcnt[batch[i]], 1.f);
}

// ---------- exclusive scan of (deg+1); last block scans the block sums -----------
__global__ void k_scan1(int n, int nb) {
  __shared__ int sh[SCAN_B];
  __shared__ int lastblk;
  int t = threadIdx.x;
  int i = blockIdx.x * SCAN_B + t;
  int v = (i < n) ? (g_deg[i] + 1) : 0;   // +1 = self loop
  sh[t] = v;
  __syncthreads();
#pragma unroll
  for (int o = 1; o < SCAN_B; o <<= 1) {
    int x = (t >= o) ? sh[t - o] : 0;
    __syncthreads();
    sh[t] += x;
    __syncthreads();
  }
  if (i < n) g_rp[i] = sh[t] - v;              // exclusive, pre block-offset
  if (t == SCAN_B - 1) {
    g_bsum[blockIdx.x] = sh[t];
    __threadfence();                            // bsum visible before ticket
    int r = atomicAdd(&g_ctr1, 1);
    lastblk = (r == (int)gridDim.x - 1);
  }
  __syncthreads();
  if (lastblk) {                                // last block: scan the block sums
    int v2 = (t < nb) ? g_bsum[t] : 0;
    sh[t] = v2;
    __syncthreads();
#pragma unroll
    for (int o = 1; o < SCAN_B; o <<= 1) {
      int x = (t >= o) ? sh[t - o] : 0;
      __syncthreads();
      sh[t] += x;
      __syncthreads();
    }
    if (t < nb) g_boff[t] = sh[t] - v2;
    if (t == 0) g_ctr1 = 0;                     // restore invariant
  }
}

// 4 edges per thread; self-loops appended in the same grid.
// final row start = g_rp[d] + g_boff[d>>9].
__global__ void k_scatter(const int* __restrict__ ei, int E, int n) {
  int i = blockIdx.x * blockDim.x + threadIdx.x;
  int E4 = E >> 2;
  if (i < E4) {
    int4 s = ((const int4*)ei)[i];
    int4 d = ((const int4*)(ei + E))[i];
    int px = atomicAdd(&g_fill[d.x], 1);
    int py = atomicAdd(&g_fill[d.y], 1);
    int pz = atomicAdd(&g_fill[d.z], 1);
    int pw = atomicAdd(&g_fill[d.w], 1);
    g_csrc[g_rp[d.x] + g_boff[d.x >> 9] + px] = s.x;
    g_csrc[g_rp[d.y] + g_boff[d.y >> 9] + py] = s.y;
    g_csrc[g_rp[d.z] + g_boff[d.z >> 9] + pz] = s.z;
    g_csrc[g_rp[d.w] + g_boff[d.w >> 9] + pw] = s.w;
  } else {
    int tail = E - (E4 << 2);
    int j = i - E4;
    if (j < tail) {
      int jj = (E4 << 2) + j;
      int s = ei[jj], d = ei[E + jj];
      int pos = atomicAdd(&g_fill[d], 1);
      g_csrc[g_rp[d] + g_boff[d >> 9] + pos] = s;
    } else {
      int v = j - tail;
      if (v < n) {
        int pos = atomicAdd(&g_fill[v], 1);
        g_csrc[g_rp[v] + g_boff[v >> 9] + pos] = v;   // self loop
      }
    }
  }
}

// ---------------- GEMM + fused attention dots -----------------------------------
__global__ void k_gemm(const float* __restrict__ Xin, int insel,
                       const float* __restrict__ W,
                       const float* __restrict__ asrc,
                       const float* __restrict__ adst, int n, int fin) {
  const float* X = Xin ? Xin : (insel ? g_f1 : g_f0);
  __shared__ float xs[32 * 128];
  int tid = threadIdx.x;
  int lane = tid & 31;
  int row0 = blockIdx.x * 32;
  int fin4 = fin >> 2;
  int nf4 = 32 * fin4;
  const float4* X4 = (const float4*)X;
  for (int i = tid; i < nf4; i += 128) {
    int row = i / fin4;
    int kk = i - row * fin4;
    float4 v = make_float4(0.f, 0.f, 0.f, 0.f);
    if (row0 + row < n) v = X4[(row0 + row) * fin4 + kk];
    ((float4*)xs)[i] = v;
  }
  __syncthreads();
  int colg = lane;
  int rowseg = tid >> 5;
  unsigned long long acc[8][2];
#pragma unroll
  for (int r = 0; r < 8; r++) { acc[r][0] = 0ULL; acc[r][1] = 0ULL; }
  const float* xb = &xs[(rowseg * 8) * fin];
  const float* wb = &W[colg * 4];
  for (int k = 0; k < fin; k += 4) {
    ulonglong2 w0 = *(const ulonglong2*)&wb[(k + 0) * 128];
    ulonglong2 w1 = *(const ulonglong2*)&wb[(k + 1) * 128];
    ulonglong2 w2 = *(const ulonglong2*)&wb[(k + 2) * 128];
    ulonglong2 w3 = *(const ulonglong2*)&wb[(k + 3) * 128];
#pragma unroll
    for (int r = 0; r < 8; r++) {
      float4 x4 = *(const float4*)&xb[r * fin + k];
      unsigned long long xx;
      PACK2(xx, x4.x); FMA2(acc[r][0], xx, w0.x); FMA2(acc[r][1], xx, w0.y);
      PACK2(xx, x4.y); FMA2(acc[r][0], xx, w1.x); FMA2(acc[r][1], xx, w1.y);
      PACK2(xx, x4.z); FMA2(acc[r][0], xx, w2.x); FMA2(acc[r][1], xx, w2.y);
      PACK2(xx, x4.w); FMA2(acc[r][0], xx, w3.x); FMA2(acc[r][1], xx, w3.y);
    }
  }
  float4 as4 = *(const float4*)&asrc[colg * 4];
  float4 ad4 = *(const float4*)&adst[colg * 4];
#pragma unroll
  for (int r = 0; r < 8; r++) {
    int row = row0 + rowseg * 8 + r;
    unsigned a, b, c, d;
    UNPACK2(a, b, acc[r][0]);
    UNPACK2(c, d, acc[r][1]);
    float4 hv = make_float4(__uint_as_float(a), __uint_as_float(b),
                            __uint_as_float(c), __uint_as_float(d));
    float ss = hv.x * as4.x + hv.y * as4.y + hv.z * as4.z + hv.w * as4.w;
    float sd = hv.x * ad4.x + hv.y * ad4.y + hv.z * ad4.z + hv.w * ad4.w;
#pragma unroll
    for (int o = 8; o; o >>= 1) {
      ss += __shfl_xor_sync(0xffffffffu, ss, o);
      sd += __shfl_xor_sync(0xffffffffu, sd, o);
    }
    float ss1 = __shfl_sync(0xffffffffu, ss, 16);
    float sd1 = __shfl_sync(0xffffffffu, sd, 16);
    if (row < n) {
      half2 p0 = __floats2half2_rn(hv.x, hv.y);
      half2 p1 = __floats2half2_rn(hv.z, hv.w);
      uint2 hp;
      hp.x = *(unsigned*)&p0;
      hp.y = *(unsigned*)&p1;
      g_h16[row * 32 + colg] = hp;
      if (lane == 0) *(float4*)&g_att[4 * row] = make_float4(ss, ss1, sd, sd1);
    }
  }
}

// ------ softmax + aggregate + head-mean + bias + relu (+ fused pool & final) -----
// lw==nullptr: write node features. lw!=nullptr (layer 3): fused pool dot, zero
// deg/fill (zero-at-exit), and the last-finishing block computes the final output.
__global__ void k_agg(const float* __restrict__ bias, int outsel, int n,
                      const float* __restrict__ lw, const int* __restrict__ batch,
                      const float* __restrict__ lb, float* __restrict__ out, int G) {
  __shared__ int lastblk;
  float* OUT = outsel ? g_f1 : g_f0;
  int v = blockIdx.x * 8 + (threadIdx.x >> 5);
  int lane = threadIdx.x & 31;
  bool active = (v < n);

  if (active) {
    int rs = g_rp[v] + g_boff[v >> 9];
    int re = rs + g_deg[v] + 1;                 // +1 self loop
    float2 adv = *(const float2*)&g_att[4 * v + 2];
    bool head1 = lane >= 16;

    float s0 = 0.f, s1 = 0.f;
    float4 acc = make_float4(0.f, 0.f, 0.f, 0.f);
    for (int base = rs; base < re; base += 32) {
      int jj = base + lane;
      int s_l = 0;
      float x0 = 0.f, x1 = 0.f;
      if (jj < re) {
        s_l = g_csrc[jj];                                 // coalesced
        float2 as = *(const float2*)&g_att[4 * s_l];      // independent gathers
        float e0 = as.x + adv.x; e0 = fmaxf(e0, 0.2f * e0);
        float e1 = as.y + adv.y; e1 = fmaxf(e1, 0.2f * e1);
        x0 = __expf(e0); x1 = __expf(e1);
      }
      s0 += x0; s1 += x1;
      int cnt = min(re - base, 32);
#pragma unroll 4
      for (int k = 0; k < cnt; k++) {
        int s = __shfl_sync(0xffffffffu, s_l, k);
        float xa = __shfl_sync(0xffffffffu, x0, k);
        float xb = __shfl_sync(0xffffffffu, x1, k);
        float xw = head1 ? xb : xa;
        uint2 hp = g_h16[s * 32 + lane];                  // independent 256B/warp
        float2 f0 = __half22float2(*(half2*)&hp.x);
        float2 f1 = __half22float2(*(half2*)&hp.y);
        acc.x += xw * f0.x; acc.y += xw * f0.y;
        acc.z += xw * f1.x; acc.w += xw * f1.y;
      }
    }
#pragma unroll
    for (int o = 16; o; o >>= 1) {
      s0 += __shfl_xor_sync(0xffffffffu, s0, o);
      s1 += __shfl_xor_sync(0xffffffffu, s1, o);
    }
    float r0 = 0.5f / fmaxf(s0, 1e-16f);
    float r1 = 0.5f / fmaxf(s1, 1e-16f);
    float rw = head1 ? r1 : r0;
    acc.x *= rw; acc.y *= rw; acc.z *= rw; acc.w *= rw;
    float px = __shfl_xor_sync(0xffffffffu, acc.x, 16);
    float py = __shfl_xor_sync(0xffffffffu, acc.y, 16);
    float pz = __shfl_xor_sync(0xffffffffu, acc.z, 16);
    float pw = __shfl_xor_sync(0xffffffffu, acc.w, 16);
    float pdot = 0.f;
    if (!head1) {
      float4 b4 = *(const float4*)&bias[lane * 4];
      float4 o;
      o.x = fmaxf(acc.x + px + b4.x, 0.f);
      o.y = fmaxf(acc.y + py + b4.y, 0.f);
      o.z = fmaxf(acc.z + pz + b4.z, 0.f);
      o.w = fmaxf(acc.w + pw + b4.w, 0.f);
      if (!lw) {
        *(float4*)&OUT[v * 64 + lane * 4] = o;
      } else {
        float4 w4 = *(const float4*)&lw[lane * 4];
        pdot = o.x * w4.x + o.y * w4.y + o.z * w4.z + o.w * w4.w;
      }
    }
    if (lw) {
#pragma unroll
      for (int o = 8; o; o >>= 1) pdot += __shfl_xor_sync(0xffffffffu, pdot, o);
      if (lane == 0) {
        atomicAdd(&g_gsum[batch[v]], pdot);
        g_deg[v] = 0;                           // zero-at-exit
        g_fill[v] = 0;
        __threadfence();                        // order red+stores before ticket
      }
    }
  }

  if (lw) {                                     // fused final: last block wins
    __syncthreads();
    if (threadIdx.x == 0) {
      int r = atomicAdd(&g_ctr2, 1);
      lastblk = (r == (int)gridDim.x - 1);
    }
    __syncthreads();
    if (lastblk) {
      float lbv = lb[0];
      for (int i = threadIdx.x; i < G; i += blockDim.x) {
        float s = *(volatile float*)&g_gsum[i];
        float c = *(volatile float*)&g_gcnt[i];
        out[i] = s / fmaxf(c, 1.f) + lbv;
        g_gsum[i] = 0.f;                        // zero-at-exit
        g_gcnt[i] = 0.f;
      }
      if (threadIdx.x == 0) g_ctr2 = 0;
    }
  }
}

// ---------------- launch ----------------------------------------------------------
extern "C" void kernel_launch(void* const* d_in, const int* in_sizes, int n_in,
                              void* d_out, int out_size) {
  int base;
  const int *ei, *bat;
  int Esz;
  if (in_sizes[1] > 1000000) {          // dict order: x, edge_index, batch, ...
    ei = (const int*)d_in[1];
    bat = (const int*)d_in[2];
    base = 3;
    Esz = in_sizes[1];
  } else {                               // signature order
    base = 1;
    ei = (const int*)d_in[15];
    bat = (const int*)d_in[16];
    Esz = in_sizes[15];
  }
  const float* x   = (const float*)d_in[0];
  const float* W1  = (const float*)d_in[base + 0];
  const float* as1 = (const float*)d_in[base + 1];
  const float* ad1 = (const float*)d_in[base + 2];
  const float* b1  = (const float*)d_in[base + 3];
  const float* W2  = (const float*)d_in[base + 4];
  const float* as2 = (const float*)d_in[base + 5];
  const float* ad2 = (const float*)d_in[base + 6];
  const float* b2  = (const float*)d_in[base + 7];
  const float* W3  = (const float*)d_in[base + 8];
  const float* as3 = (const float*)d_in[base + 9];
  const float* ad3 = (const float*)d_in[base + 10];
  const float* b3  = (const float*)d_in[base + 11];
  const float* lw  = (const float*)d_in[base + 12];
  const float* lb  = (const float*)d_in[base + 13];

  int n = in_sizes[0] / 128;
  int E = Esz / 2;
  int G = out_size;

  const int tb = 256;
  int gb = (n + 31) / 32;
  int wg = (n + 7) / 8;
  int E4 = E >> 2;
  int tailE = E - (E4 << 2);
  int nb = (n + SCAN_B - 1) / SCAN_B;
  int cntGrid = ((E4 + tailE > n ? E4 + tailE : n) + tb - 1) / tb;

  // CSR build (relies on zero-at-exit invariant of deg/fill/gsum/gcnt/tickets)
  k_count<<<cntGrid, tb>>>(ei, bat, E, n);
  k_scan1<<<nb, SCAN_B>>>(n, nb);
  k_scatter<<<(E4 + tailE + n + tb - 1) / tb, tb>>>(ei, E, n);

  k_gemm<<<gb, 128>>>(x, 0, W1, as1, ad1, n, 128);
  k_agg<<<wg, 256>>>(b1, 0, n, nullptr, nullptr, nullptr, nullptr, 0);
  k_gemm<<<gb, 128>>>(nullptr, 0, W2, as2, ad2, n, 64);
  k_agg<<<wg, 256>>>(b2, 1, n, nullptr, nullptr, nullptr, nullptr, 0);
  k_gemm<<<gb, 128>>>(nullptr, 1, W3, as3, ad3, n, 64);
  k_agg<<<wg, 256>>>(b3, 0, n, lw, bat, lb, (float*)d_out, G);  // + fused final
}

// round 9
// speedup vs baseline: 1.1706x; 1.1706x over previous
#include <cuda_runtime.h>
#include <cuda_fp16.h>

#define NMAX 50000
#define EMAX 800000
#define GMAX 2500
#define ETOT (EMAX + NMAX)
#define SCAN_B 512
#define SCAN_NB ((NMAX + SCAN_B - 1) / SCAN_B)   // 98

// packed dual-fp32 helpers (sm_100+ PTX)
#define PACK2(out, f) asm("mov.b64 %0, {%1, %1};" : "=l"(out) : "r"(__float_as_uint(f)))
#define FMA2(d, a, b) asm("fma.rn.f32x2 %0, %1, %2, %0;" : "+l"(d) : "l"(a), "l"(b))
#define UNPACK2(lo, hi, v) asm("mov.b64 {%0, %1}, %2;" : "=r"(lo), "=r"(hi) : "l"(v))

// ---------------- scratch (device globals; no allocation allowed) ----------------
__device__ uint2 g_h16[NMAX * 32];     // per-layer hidden, fp16
__device__ float g_f0[NMAX * 64];      // layer output ping (fp32)
__device__ float g_f1[NMAX * 64];      // layer output pong
__device__ float g_att[NMAX * 4];      // per node: a_src0, a_src1, a_dst0, a_dst1
__device__ int   g_rp[NMAX + 1];       // CSR row_ptr (pre block-offset)
__device__ int   g_deg[NMAX];
__device__ int   g_fill[NMAX];
__device__ int   g_csrc[ETOT];         // CSR src indices
__device__ float g_gsum[GMAX];
__device__ float g_gcnt[GMAX];
__device__ int   g_bsum[SCAN_NB + 1];
__device__ int   g_boff[SCAN_NB + 1];

// ---------------- CSR build (dst is layer-invariant) + pool zero/count -----------
__global__ void k_init(int n, int g) {
  int i = blockIdx.x * blockDim.x + threadIdx.x;
  if (i < n) { g_deg[i] = 1; g_fill[i] = 0; }   // 1 = self loop
  if (i < g) { g_gsum[i] = 0.f; g_gcnt[i] = 0.f; }
}

// 4 edges/thread deg-count + graph-size count for mean pooling (merged)
__global__ void k_count(const int* __restrict__ ei, const int* __restrict__ batch,
                        int E, int n) {
  int i = blockIdx.x * blockDim.x + threadIdx.x;
  int E4 = E >> 2;
  if (i < E4) {
    int4 d = ((const int4*)(ei + E))[i];
    atomicAdd(&g_deg[d.x], 1);
    atomicAdd(&g_deg[d.y], 1);
    atomicAdd(&g_deg[d.z], 1);
    atomicAdd(&g_deg[d.w], 1);
  } else {
    int j = (E4 << 2) + (i - E4);
    if (j < E) atomicAdd(&g_deg[ei[E + j]], 1);
  }
  if (i < n) atomicAdd(&g_gcnt[batch[i]], 1.f);
}

// ---------- 2-phase exclusive scan of g_deg (block offsets kept separate) --------
__global__ void k_scan1(int n) {
  __shared__ int sh[SCAN_B];
  int t = threadIdx.x;
  int i = blockIdx.x * SCAN_B + t;
  int v = (i < n) ? g_deg[i] : 0;
  sh[t] = v;
  __syncthreads();
#pragma unroll
  for (int o = 1; o < SCAN_B; o <<= 1) {
    int x = (t >= o) ? sh[t - o] : 0;
    __syncthreads();
    sh[t] += x;
    __syncthreads();
  }
  if (i < n) g_rp[i] = sh[t] - v;            // exclusive, pre block-offset
  if (t == SCAN_B - 1) g_bsum[blockIdx.x] = sh[t];
}

__global__ void k_scan2(int nb) {
  __shared__ int sh[128];
  int t = threadIdx.x;
  int v = (t < nb) ? g_bsum[t] : 0;
  sh[t] = v;
  __syncthreads();
#pragma unroll
  for (int o = 1; o < 128; o <<= 1) {
    int x = (t >= o) ? sh[t - o] : 0;
    __syncthreads();
    sh[t] += x;
    __syncthreads();
  }
  if (t < nb) g_boff[t] = sh[t] - v;          // exclusive block offsets
}

// 4 edges per thread; self-loops appended in the same grid.
__global__ void k_scatter(const int* __restrict__ ei, int E, int n) {
  int i = blockIdx.x * blockDim.x + threadIdx.x;
  int E4 = E >> 2;
  if (i < E4) {
    int4 s = ((const int4*)ei)[i];
    int4 d = ((const int4*)(ei + E))[i];
    int px = atomicAdd(&g_fill[d.x], 1);
    int py = atomicAdd(&g_fill[d.y], 1);
    int pz = atomicAdd(&g_fill[d.z], 1);
    int pw = atomicAdd(&g_fill[d.w], 1);
    g_csrc[g_rp[d.x] + g_boff[d.x >> 9] + px] = s.x;
    g_csrc[g_rp[d.y] + g_boff[d.y >> 9] + py] = s.y;
    g_csrc[g_rp[d.z] + g_boff[d.z >> 9] + pz] = s.z;
    g_csrc[g_rp[d.w] + g_boff[d.w >> 9] + pw] = s.w;
  } else {
    int tail = E - (E4 << 2);
    int j = i - E4;
    if (j < tail) {
      int jj = (E4 << 2) + j;
      int s = ei[jj], d = ei[E + jj];
      int pos = atomicAdd(&g_fill[d], 1);
      g_csrc[g_rp[d] + g_boff[d >> 9] + pos] = s;
    } else {
      int v = j - tail;
      if (v < n) {
        int pos = atomicAdd(&g_fill[v], 1);
        g_csrc[g_rp[v] + g_boff[v >> 9] + pos] = v;   // self loop
      }
    }
  }
}

// ---------------- GEMM + fused attention dots -----------------------------------
// Software-pipelined W loads: iteration k's FMA block runs while k+1's four
// LDG.128 are in flight (removes the dependent load->FMA stall each chunk).
__global__ void k_gemm(const float* __restrict__ Xin, int insel,
                       const float* __restrict__ W,
                       const float* __restrict__ asrc,
                       const float* __restrict__ adst, int n, int fin) {
  const float* X = Xin ? Xin : (insel ? g_f1 : g_f0);
  __shared__ float xs[32 * 128];
  int tid = threadIdx.x;
  int lane = tid & 31;
  int row0 = blockIdx.x * 32;
  int fin4 = fin >> 2;
  int nf4 = 32 * fin4;
  const float4* X4 = (const float4*)X;
  for (int i = tid; i < nf4; i += 128) {
    int row = i / fin4;
    int kk = i - row * fin4;
    float4 v = make_float4(0.f, 0.f, 0.f, 0.f);
    if (row0 + row < n) v = X4[(row0 + row) * fin4 + kk];
    ((float4*)xs)[i] = v;
  }
  __syncthreads();
  int colg = lane;
  int rowseg = tid >> 5;
  unsigned long long acc[8][2];
#pragma unroll
  for (int r = 0; r < 8; r++) { acc[r][0] = 0ULL; acc[r][1] = 0ULL; }
  const float* xb = &xs[(rowseg * 8) * fin];
  const float* wb = &W[colg * 4];

  // prologue: load k=0 chunk
  ulonglong2 w0 = *(const ulonglong2*)&wb[0 * 128];
  ulonglong2 w1 = *(const ulonglong2*)&wb[1 * 128];
  ulonglong2 w2 = *(const ulonglong2*)&wb[2 * 128];
  ulonglong2 w3 = *(const ulonglong2*)&wb[3 * 128];

  for (int k = 0; k < fin; k += 4) {
    // prefetch next chunk's W before consuming the current one
    ulonglong2 n0 = w0, n1 = w1, n2 = w2, n3 = w3;
    int kn = k + 4;
    if (kn < fin) {
      n0 = *(const ulonglong2*)&wb[(kn + 0) * 128];
      n1 = *(const ulonglong2*)&wb[(kn + 1) * 128];
      n2 = *(const ulonglong2*)&wb[(kn + 2) * 128];
      n3 = *(const ulonglong2*)&wb[(kn + 3) * 128];
    }
#pragma unroll
    for (int r = 0; r < 8; r++) {
      float4 x4 = *(const float4*)&xb[r * fin + k];
      unsigned long long xx;
      PACK2(xx, x4.x); FMA2(acc[r][0], xx, w0.x); FMA2(acc[r][1], xx, w0.y);
      PACK2(xx, x4.y); FMA2(acc[r][0], xx, w1.x); FMA2(acc[r][1], xx, w1.y);
      PACK2(xx, x4.z); FMA2(acc[r][0], xx, w2.x); FMA2(acc[r][1], xx, w2.y);
      PACK2(xx, x4.w); FMA2(acc[r][0], xx, w3.x); FMA2(acc[r][1], xx, w3.y);
    }
    w0 = n0; w1 = n1; w2 = n2; w3 = n3;
  }
  // epilogue: attention dots (fp32 exact) + fp16 h store
  float4 as4 = *(const float4*)&asrc[colg * 4];
  float4 ad4 = *(const float4*)&adst[colg * 4];
#pragma unroll
  for (int r = 0; r < 8; r++) {
    int row = row0 + rowseg * 8 + r;
    unsigned a, b, c, d;
    UNPACK2(a, b, acc[r][0]);
    UNPACK2(c, d, acc[r][1]);
    float4 hv = make_float4(__uint_as_float(a), __uint_as_float(b),
                            __uint_as_float(c), __uint_as_float(d));
    float ss = hv.x * as4.x + hv.y * as4.y + hv.z * as4.z + hv.w * as4.w;
    float sd = hv.x * ad4.x + hv.y * ad4.y + hv.z * ad4.z + hv.w * ad4.w;
#pragma unroll
    for (int o = 8; o; o >>= 1) {
      ss += __shfl_xor_sync(0xffffffffu, ss, o);
      sd += __shfl_xor_sync(0xffffffffu, sd, o);
    }
    float ss1 = __shfl_sync(0xffffffffu, ss, 16);
    float sd1 = __shfl_sync(0xffffffffu, sd, 16);
    if (row < n) {
      half2 p0 = __floats2half2_rn(hv.x, hv.y);
      half2 p1 = __floats2half2_rn(hv.z, hv.w);
      uint2 hp;
      hp.x = *(unsigned*)&p0;
      hp.y = *(unsigned*)&p1;
      g_h16[row * 32 + colg] = hp;
      if (lane == 0) *(float4*)&g_att[4 * row] = make_float4(ss, ss1, sd, sd1);
    }
  }
}

// ---------------- softmax + aggregate + head-mean + bias + relu ------------------
__global__ void k_agg(const float* __restrict__ bias, int outsel, int n,
                      const float* __restrict__ lw, const int* __restrict__ batch) {
  float* OUT = outsel ? g_f1 : g_f0;
  int v = blockIdx.x * 8 + (threadIdx.x >> 5);
  int lane = threadIdx.x & 31;
  if (v >= n) return;
  int rs = g_rp[v] + g_boff[v >> 9];
  int re = rs + g_deg[v];
  float2 adv = *(const float2*)&g_att[4 * v + 2];
  bool head1 = lane >= 16;

  float s0 = 0.f, s1 = 0.f;
  float4 acc = make_float4(0.f, 0.f, 0.f, 0.f);
  for (int base = rs; base < re; base += 32) {
    int jj = base + lane;
    int s_l = 0;
    float x0 = 0.f, x1 = 0.f;
    if (jj < re) {
      s_l = g_csrc[jj];                                 // coalesced
      float2 as = *(const float2*)&g_att[4 * s_l];      // independent gathers
      float e0 = as.x + adv.x; e0 = fmaxf(e0, 0.2f * e0);
      float e1 = as.y + adv.y; e1 = fmaxf(e1, 0.2f * e1);
      x0 = __expf(e0); x1 = __expf(e1);
    }
    s0 += x0; s1 += x1;
    int cnt = min(re - base, 32);
#pragma unroll 4
    for (int k = 0; k < cnt; k++) {
      int s = __shfl_sync(0xffffffffu, s_l, k);
      float xa = __shfl_sync(0xffffffffu, x0, k);
      float xb = __shfl_sync(0xffffffffu, x1, k);
      float xw = head1 ? xb : xa;
      uint2 hp = g_h16[s * 32 + lane];                  // independent 256B/warp
      float2 f0 = __half22float2(*(half2*)&hp.x);
      float2 f1 = __half22float2(*(half2*)&hp.y);
      acc.x += xw * f0.x; acc.y += xw * f0.y;
      acc.z += xw * f1.x; acc.w += xw * f1.y;
    }
  }
#pragma unroll
  for (int o = 16; o; o >>= 1) {
    s0 += __shfl_xor_sync(0xffffffffu, s0, o);
    s1 += __shfl_xor_sync(0xffffffffu, s1, o);
  }
  float r0 = 0.5f / fmaxf(s0, 1e-16f);
  float r1 = 0.5f / fmaxf(s1, 1e-16f);
  float rw = head1 ? r1 : r0;
  acc.x *= rw; acc.y *= rw; acc.z *= rw; acc.w *= rw;
  float px = __shfl_xor_sync(0xffffffffu, acc.x, 16);
  float py = __shfl_xor_sync(0xffffffffu, acc.y, 16);
  float pz = __shfl_xor_sync(0xffffffffu, acc.z, 16);
  float pw = __shfl_xor_sync(0xffffffffu, acc.w, 16);
  float pdot = 0.f;
  if (!head1) {
    float4 b4 = *(const float4*)&bias[lane * 4];
    float4 o;
    o.x = fmaxf(acc.x + px + b4.x, 0.f);
    o.y = fmaxf(acc.y + py + b4.y, 0.f);
    o.z = fmaxf(acc.z + pz + b4.z, 0.f);
    o.w = fmaxf(acc.w + pw + b4.w, 0.f);
    if (!lw) {
      *(float4*)&OUT[v * 64 + lane * 4] = o;
    } else {
      float4 w4 = *(const float4*)&lw[lane * 4];
      pdot = o.x * w4.x + o.y * w4.y + o.z * w4.z + o.w * w4.w;
    }
  }
  if (lw) {
#pragma unroll
    for (int o = 8; o; o >>= 1) pdot += __shfl_xor_sync(0xffffffffu, pdot, o);
    if (lane == 0) atomicAdd(&g_gsum[batch[v]], pdot);
  }
}

// ---------------- final linear -----------------------------------------
__global__ void k_final(const float* __restrict__ lb, float* __restrict__ out, int g) {
  int i = blockIdx.x * blockDim.x + threadIdx.x;
  if (i < g) out[i] = g_gsum[i] / fmaxf(g_gcnt[i], 1.f) + lb[0];
}

// ---------------- launch ----------------------------------------------------------
extern "C" void kernel_launch(void* const* d_in, const int* in_sizes, int n_in,
                              void* d_out, int out_size) {
  int base;
  const int *ei, *bat;
  int Esz;
  if (in_sizes[1] > 1000000) {          // dict order: x, edge_index, batch, ...
    ei = (const int*)d_in[1];
    bat = (const int*)d_in[2];
    base = 3;
    Esz = in_sizes[1];
  } else {                               // signature order
    base = 1;
    ei = (const int*)d_in[15];
    bat = (const int*)d_in[16];
    Esz = in_sizes[15];
  }
  const float* x   = (const float*)d_in[0];
  const float* W1  = (const float*)d_in[base + 0];
  const float* as1 = (const float*)d_in[base + 1];
  const float* ad1 = (const float*)d_in[base + 2];
  const float* b1  = (const float*)d_in[base + 3];
  const float* W2  = (const float*)d_in[base + 4];
  const float* as2 = (const float*)d_in[base + 5];
  const float* ad2 = (const float*)d_in[base + 6];
  const float* b2  = (const float*)d_in[base + 7];
  const float* W3  = (const float*)d_in[base + 8];
  const float* as3 = (const float*)d_in[base + 9];
  const float* ad3 = (const float*)d_in[base + 10];
  const float* b3  = (const float*)d_in[base + 11];
  const float* lw  = (const float*)d_in[base + 12];
  const float* lb  = (const float*)d_in[base + 13];

  int n = in_sizes[0] / 128;
  int E = Esz / 2;
  int G = out_size;

  const int tb = 256;
  int gb = (n + 31) / 32;
  int wg = (n + 7) / 8;
  int E4 = E >> 2;
  int tailE = E - (E4 << 2);
  int nb = (n + SCAN_B - 1) / SCAN_B;
  int cntGrid = ((E4 + tailE > n ? E4 + tailE : n) + tb - 1) / tb;

  // CSR build
  k_init<<<(n + tb - 1) / tb, tb>>>(n, G);
  k_count<<<cntGrid, tb>>>(ei, bat, E, n);
  k_scan1<<<nb, SCAN_B>>>(n);
  k_scan2<<<1, 128>>>(nb);
  k_scatter<<<(E4 + tailE + n + tb - 1) / tb, tb>>>(ei, E, n);

  k_gemm<<<gb, 128>>>(x, 0, W1, as1, ad1, n, 128);
  k_agg<<<wg, 256>>>(b1, 0, n, nullptr, nullptr);
  k_gemm<<<gb, 128>>>(nullptr, 0, W2, as2, ad2, n, 64);
  k_agg<<<wg, 256>>>(b2, 1, n, nullptr, nullptr);
  k_gemm<<<gb, 128>>>(nullptr, 1, W3, as3, ad3, n, 64);
  k_agg<<<wg, 256>>>(b3, 0, n, lw, bat);        // fused global-mean-pool dot

  k_final<<<(G + tb - 1) / tb, tb>>>(lb, (float*)d_out, G);
}